// round 4
// baseline (speedup 1.0000x reference)
#include <cuda_runtime.h>
#include <cuda_bf16.h>
#include <math.h>
#include <stdint.h>

// ---------------------------------------------------------------------------
// Shapes: B=8192, I=512, H=1024, N=4096, K=1536, K_eff=3*1536=4608
// gates = x@Wi + h@Wh (bias folded into LN); per-gate LayerNorm; LSTM math.
// GEMM: bf16 split (3 first-order terms) via mma.sync.m16n8k16, fp32 accum.
// Tile 128x256x64, warp tile 64x64, 4-stage cp.async.
// ---------------------------------------------------------------------------
#define B_DIM 8192
#define I_DIM 512
#define H_DIM 1024
#define N_DIM 4096
#define K_RAW 1536
#define K_EFF 4608

__device__ float g_gates[(size_t)B_DIM * N_DIM];                        // 128 MB
__device__ __align__(1024) __nv_bfloat16 g_Acat[(size_t)B_DIM * K_EFF]; // 75 MB
__device__ __align__(1024) __nv_bfloat16 g_Wcat[(size_t)N_DIM * K_EFF]; // 38 MB

// ------------------------------ PTX helpers --------------------------------
__device__ __forceinline__ uint32_t smem_u32(const void* p) {
    uint32_t a;
    asm("{ .reg .u64 t; cvta.to.shared.u64 t, %1; cvt.u32.u64 %0, t; }"
        : "=r"(a) : "l"(p));
    return a;
}

__device__ __forceinline__ void cp16(uint32_t dst, const void* src) {
    asm volatile("cp.async.cg.shared.global [%0], [%1], 16;"
                 :: "r"(dst), "l"(src) : "memory");
}
#define CP_COMMIT() asm volatile("cp.async.commit_group;" ::: "memory")
#define CP_WAIT2()  asm volatile("cp.async.wait_group 2;"  ::: "memory")

#define LDSM_X4(r, addr)                                                      \
    asm volatile("ldmatrix.sync.aligned.m8n8.x4.shared.b16 {%0,%1,%2,%3}, [%4];" \
        : "=r"((r)[0]), "=r"((r)[1]), "=r"((r)[2]), "=r"((r)[3]) : "r"(addr))

#define MMA16816(d, a, b0, b1)                                                \
    asm volatile("mma.sync.aligned.m16n8k16.row.col.f32.bf16.bf16.f32 "       \
        "{%0,%1,%2,%3}, {%4,%5,%6,%7}, {%8,%9}, {%0,%1,%2,%3};"               \
        : "+f"((d)[0]), "+f"((d)[1]), "+f"((d)[2]), "+f"((d)[3])              \
        : "r"((a)[0]), "r"((a)[1]), "r"((a)[2]), "r"((a)[3]),                 \
          "r"(b0), "r"(b1))

// ---------------------------------------------------------------------------
// Pack kernels: split-bf16 operands.
//   A_cat[b][k'] = [hi | lo | hi] of (x|h)[b]
//   W_cat[n][k'] = [hi | hi | lo] of W[.][n]  (K-major, transposed)
// ---------------------------------------------------------------------------
__global__ __launch_bounds__(256)
void pack_a_kernel(const float* __restrict__ x, const float* __restrict__ h) {
    const int b = blockIdx.y;
    const int k = blockIdx.x * 256 + threadIdx.x;
    float v = (k < I_DIM) ? x[(size_t)b * I_DIM + k]
                          : h[(size_t)b * H_DIM + (k - I_DIM)];
    __nv_bfloat16 hi = __float2bfloat16(v);
    __nv_bfloat16 lo = __float2bfloat16(v - __bfloat162float(hi));
    const size_t base = (size_t)b * K_EFF;
    g_Acat[base + k]             = hi;
    g_Acat[base + K_RAW + k]     = lo;
    g_Acat[base + 2 * K_RAW + k] = hi;
}

__global__ __launch_bounds__(256)
void pack_w_kernel(const float* __restrict__ Wi, const float* __restrict__ Wh) {
    __shared__ float t[32][33];
    const int k0 = blockIdx.x * 32;
    const int n0 = blockIdx.y * 32;
    const int tx = threadIdx.x, ty = threadIdx.y; // 32 x 8
#pragma unroll
    for (int i = 0; i < 4; ++i) {
        const int k = k0 + ty + i * 8;
        const int n = n0 + tx;
        float v = (k < I_DIM) ? Wi[(size_t)k * N_DIM + n]
                              : Wh[(size_t)(k - I_DIM) * N_DIM + n];
        t[ty + i * 8][tx] = v;
    }
    __syncthreads();
#pragma unroll
    for (int i = 0; i < 4; ++i) {
        const int n = n0 + ty + i * 8;
        const int k = k0 + tx;
        float v = t[tx][ty + i * 8];
        __nv_bfloat16 hi = __float2bfloat16(v);
        __nv_bfloat16 lo = __float2bfloat16(v - __bfloat162float(hi));
        const size_t base = (size_t)n * K_EFF;
        g_Wcat[base + k]             = hi;
        g_Wcat[base + K_RAW + k]     = hi;
        g_Wcat[base + 2 * K_RAW + k] = lo;
    }
}

// ---------------------------------------------------------------------------
// bf16 TN GEMM: gates[M,N] = A_cat[M,K] @ W_cat[N,K]^T
//   CTA 128x256x64, 256 thr, 8 warps (2m x 4n), warp tile 64x64.
//   4-stage cp.async pipeline, XOR-swizzled smem, ldmatrix + mma.m16n8k16.
// ---------------------------------------------------------------------------
#define STAGES 4
#define BK 64
#define TILE_M 128
#define TILE_N 256
#define NK (K_EFF / BK)              // 72
#define STAGE_BYTES 49152            // A 16KB + B 32KB
#define SMEM_BYTES (STAGES * STAGE_BYTES)   // 192 KB

__device__ __forceinline__ void issue_stage(uint32_t sbase, int s,
                                            const __nv_bfloat16* A,
                                            const __nv_bfloat16* W,
                                            int m0, int n0, int k0, int tid) {
    const uint32_t sA = sbase + s * STAGE_BYTES;
    const uint32_t sB = sA + 16384;
#pragma unroll
    for (int i = 0; i < 4; ++i) {                // A: 128 rows x 8 chunks
        const int idx = tid + 256 * i;           // 0..1023
        const int row = idx >> 3;
        const int c   = idx & 7;
        cp16(sA + row * 128 + ((c ^ (row & 7)) << 4),
             A + (size_t)(m0 + row) * K_EFF + k0 + c * 8);
    }
#pragma unroll
    for (int i = 0; i < 8; ++i) {                // B: 256 rows x 8 chunks
        const int idx = tid + 256 * i;           // 0..2047
        const int row = idx >> 3;
        const int c   = idx & 7;
        cp16(sB + row * 128 + ((c ^ (row & 7)) << 4),
             W + (size_t)(n0 + row) * K_EFF + k0 + c * 8);
    }
}

__global__ void __launch_bounds__(256, 1)
gemm_mma_kernel(const __nv_bfloat16* __restrict__ A,
                const __nv_bfloat16* __restrict__ W,
                float* __restrict__ out) {
    extern __shared__ char smem[];
    const uint32_t sbase = smem_u32(smem);

    const int tid  = threadIdx.x;
    const int wid  = tid >> 5;
    const int lane = tid & 31;
    const int warp_m = wid >> 2;     // 0..1  -> 64 rows
    const int warp_n = wid & 3;      // 0..3  -> 64 cols
    const int m0 = blockIdx.y * TILE_M;
    const int n0 = blockIdx.x * TILE_N;

    const int lrow  = (lane & 7) + ((lane >> 3) & 1) * 8;  // 0..15
    const int lhalf = lane >> 4;                           // 0/1 (k chunk)

    float acc[4][8][4];
#pragma unroll
    for (int i = 0; i < 4; ++i)
#pragma unroll
        for (int j = 0; j < 8; ++j)
#pragma unroll
            for (int e = 0; e < 4; ++e) acc[i][j][e] = 0.0f;

#pragma unroll
    for (int s = 0; s < STAGES - 1; ++s) {
        issue_stage(sbase, s, A, W, m0, n0, s * BK, tid);
        CP_COMMIT();
    }

    for (int kt = 0; kt < NK; ++kt) {
        CP_WAIT2();
        __syncthreads();

        const int knext = kt + STAGES - 1;
        if (knext < NK)
            issue_stage(sbase, knext & (STAGES - 1), A, W, m0, n0, knext * BK, tid);
        CP_COMMIT();

        const uint32_t sA = sbase + (kt & (STAGES - 1)) * STAGE_BYTES;
        const uint32_t sB = sA + 16384;

#pragma unroll
        for (int ks = 0; ks < 4; ++ks) {         // 4 x k16 per BK=64
            uint32_t a[4][4];
#pragma unroll
            for (int im = 0; im < 4; ++im) {
                const int row = warp_m * 64 + im * 16 + lrow;
                const int ch  = ks * 2 + lhalf;
                LDSM_X4(a[im], sA + row * 128 + ((ch ^ (row & 7)) << 4));
            }
            uint32_t b[4][4];
#pragma unroll
            for (int jb = 0; jb < 4; ++jb) {
                const int row = warp_n * 64 + jb * 16 + lrow;
                const int ch  = ks * 2 + lhalf;
                LDSM_X4(b[jb], sB + row * 128 + ((ch ^ (row & 7)) << 4));
            }
#pragma unroll
            for (int im = 0; im < 4; ++im)
#pragma unroll
                for (int jn = 0; jn < 8; ++jn)
                    MMA16816(acc[im][jn], a[im],
                             b[jn >> 1][jn & 1], b[jn >> 1][(jn & 1) + 2]);
        }
        __syncthreads();
    }

    // epilogue
#pragma unroll
    for (int im = 0; im < 4; ++im) {
        const int r0 = m0 + warp_m * 64 + im * 16 + (lane >> 2);
#pragma unroll
        for (int jn = 0; jn < 8; ++jn) {
            const int col = n0 + warp_n * 64 + jn * 8 + (lane & 3) * 2;
            float2 v0 = make_float2(acc[im][jn][0], acc[im][jn][1]);
            float2 v1 = make_float2(acc[im][jn][2], acc[im][jn][3]);
            *(float2*)&out[(size_t)r0 * N_DIM + col]       = v0;
            *(float2*)&out[(size_t)(r0 + 8) * N_DIM + col] = v1;
        }
    }
}

// ---------------------------------------------------------------------------
// LayerNorm (+bias) + LSTM elementwise. 2 batch rows / 256-thread block.
//   Warps 0-3: gates of row 2b ; warps 4-7: gates of row 2b+1.
// ---------------------------------------------------------------------------
__device__ __forceinline__ float sigmoidf_(float x) {
    return 1.0f / (1.0f + expf(-x));
}

__global__ __launch_bounds__(256)
void ln_lstm_kernel(const float* __restrict__ gates,  // [B, 4, H] (no bias)
                    const float* __restrict__ c,      // [B, H]
                    const float* __restrict__ bh,     // [4H]
                    const float* __restrict__ gamma,  // [4, H]
                    const float* __restrict__ beta,   // [4, H]
                    float* __restrict__ h_new,
                    float* __restrict__ c_new) {
    const int half = threadIdx.x >> 7;            // 0/1: which batch row
    const int gate = (threadIdx.x >> 5) & 3;      // 0..3
    const int lane = threadIdx.x & 31;
    const int b    = blockIdx.x * 2 + half;

    __shared__ float sh[8][H_DIM];                // [half*4+gate][H]

    const float* row  = gates + (size_t)b * N_DIM + gate * H_DIM;
    const float* brow = bh + gate * H_DIM;

    float4 v[8];
    float sum = 0.0f, sumsq = 0.0f;
#pragma unroll
    for (int i = 0; i < 8; ++i) {
        const int j = (lane + 32 * i) * 4;
        float4 g  = *(const float4*)&row[j];
        float4 bb = *(const float4*)&brow[j];
        v[i].x = g.x + bb.x; v[i].y = g.y + bb.y;
        v[i].z = g.z + bb.z; v[i].w = g.w + bb.w;
        sum   += v[i].x + v[i].y + v[i].z + v[i].w;
        sumsq += v[i].x * v[i].x + v[i].y * v[i].y
               + v[i].z * v[i].z + v[i].w * v[i].w;
    }
#pragma unroll
    for (int off = 16; off > 0; off >>= 1) {
        sum   += __shfl_xor_sync(0xffffffffu, sum,   off);
        sumsq += __shfl_xor_sync(0xffffffffu, sumsq, off);
    }
    const float inv_n = 1.0f / (float)H_DIM;
    const float mean = sum * inv_n;
    const float var  = fmaxf(sumsq * inv_n - mean * mean, 0.0f);
    const float rstd = rsqrtf(var + 1e-5f);

    const float* gam = gamma + gate * H_DIM;
    const float* bet = beta  + gate * H_DIM;
#pragma unroll
    for (int i = 0; i < 8; ++i) {
        const int j = (lane + 32 * i) * 4;
        float4 gv = *(const float4*)&gam[j];
        float4 bv = *(const float4*)&bet[j];
        float4 y;
        y.x = (v[i].x - mean) * rstd * gv.x + bv.x;
        y.y = (v[i].y - mean) * rstd * gv.y + bv.y;
        y.z = (v[i].z - mean) * rstd * gv.z + bv.z;
        y.w = (v[i].w - mean) * rstd * gv.w + bv.w;
        *(float4*)&sh[half * 4 + gate][j] = y;
    }
    __syncthreads();

    const int t128 = threadIdx.x & 127;
    const size_t base = (size_t)b * H_DIM;
#pragma unroll
    for (int ii = 0; ii < 2; ++ii) {
        const int j = (t128 + 128 * ii) * 4;
        float4 ig = *(const float4*)&sh[half * 4 + 0][j];
        float4 fg = *(const float4*)&sh[half * 4 + 1][j];
        float4 gg = *(const float4*)&sh[half * 4 + 2][j];
        float4 og = *(const float4*)&sh[half * 4 + 3][j];
        float4 cv = *(const float4*)&c[base + j];

        float4 cn, hn;
        cn.x = sigmoidf_(fg.x) * cv.x + sigmoidf_(ig.x) * tanhf(gg.x);
        cn.y = sigmoidf_(fg.y) * cv.y + sigmoidf_(ig.y) * tanhf(gg.y);
        cn.z = sigmoidf_(fg.z) * cv.z + sigmoidf_(ig.z) * tanhf(gg.z);
        cn.w = sigmoidf_(fg.w) * cv.w + sigmoidf_(ig.w) * tanhf(gg.w);
        hn.x = sigmoidf_(og.x) * tanhf(cn.x);
        hn.y = sigmoidf_(og.y) * tanhf(cn.y);
        hn.z = sigmoidf_(og.z) * tanhf(cn.z);
        hn.w = sigmoidf_(og.w) * tanhf(cn.w);

        *(float4*)&c_new[base + j] = cn;
        *(float4*)&h_new[base + j] = hn;
    }
}

// ---------------------------------------------------------------------------
// Host launcher
// ---------------------------------------------------------------------------
extern "C" void kernel_launch(void* const* d_in, const int* in_sizes, int n_in,
                              void* d_out, int out_size) {
    const float* x     = (const float*)d_in[0];
    const float* h     = (const float*)d_in[1];
    const float* c     = (const float*)d_in[2];
    const float* Wi    = (const float*)d_in[3];
    const float* Wh    = (const float*)d_in[4];
    const float* bh    = (const float*)d_in[5];
    const float* gamma = (const float*)d_in[6];
    const float* beta  = (const float*)d_in[7];

    float* out   = (float*)d_out;
    float* h_new = out;
    float* c_new = out + (size_t)B_DIM * H_DIM;

    float* gates;         cudaGetSymbolAddress((void**)&gates, g_gates);
    __nv_bfloat16* a_ptr; cudaGetSymbolAddress((void**)&a_ptr, g_Acat);
    __nv_bfloat16* w_ptr; cudaGetSymbolAddress((void**)&w_ptr, g_Wcat);

    pack_a_kernel<<<dim3(K_RAW / 256, B_DIM), 256>>>(x, h);
    pack_w_kernel<<<dim3(K_RAW / 32, N_DIM / 32), dim3(32, 8)>>>(Wi, Wh);

    cudaFuncSetAttribute(gemm_mma_kernel,
                         cudaFuncAttributeMaxDynamicSharedMemorySize, SMEM_BYTES);
    gemm_mma_kernel<<<dim3(N_DIM / TILE_N, B_DIM / TILE_M), 256, SMEM_BYTES>>>(
        a_ptr, w_ptr, gates);

    ln_lstm_kernel<<<B_DIM / 2, 256>>>(gates, c, bh, gamma, beta, h_new, c_new);
}

// round 5
// speedup vs baseline: 1.5780x; 1.5780x over previous
#include <cuda_runtime.h>
#include <cuda_bf16.h>
#include <math.h>
#include <stdint.h>

// ---------------------------------------------------------------------------
// Shapes: B=8192, I=512, H=1024, N=4096, K=1536, K_eff=3*1536=4608
// gates = x@Wi + h@Wh (bias folded into LN); per-gate LayerNorm; LSTM math.
// GEMM: bf16 split (3 first-order terms) via mma.sync.m16n8k16, fp32 accum.
// Tile 128x128x64, warp tile 64x32, 3-stage cp.async, 2 CTAs/SM.
// ---------------------------------------------------------------------------
#define B_DIM 8192
#define I_DIM 512
#define H_DIM 1024
#define N_DIM 4096
#define K_RAW 1536
#define K_EFF 4608

__device__ float g_gates[(size_t)B_DIM * N_DIM];                        // 128 MB
__device__ __align__(1024) __nv_bfloat16 g_Acat[(size_t)B_DIM * K_EFF]; // 75 MB
__device__ __align__(1024) __nv_bfloat16 g_Wcat[(size_t)N_DIM * K_EFF]; // 38 MB

// ------------------------------ PTX helpers --------------------------------
__device__ __forceinline__ uint32_t smem_u32(const void* p) {
    uint32_t a;
    asm("{ .reg .u64 t; cvta.to.shared.u64 t, %1; cvt.u32.u64 %0, t; }"
        : "=r"(a) : "l"(p));
    return a;
}

__device__ __forceinline__ void cp16(uint32_t dst, const void* src) {
    asm volatile("cp.async.cg.shared.global [%0], [%1], 16;"
                 :: "r"(dst), "l"(src) : "memory");
}
#define CP_COMMIT() asm volatile("cp.async.commit_group;" ::: "memory")
#define CP_WAIT1()  asm volatile("cp.async.wait_group 1;"  ::: "memory")

#define LDSM_X4(r, addr)                                                      \
    asm volatile("ldmatrix.sync.aligned.m8n8.x4.shared.b16 {%0,%1,%2,%3}, [%4];" \
        : "=r"((r)[0]), "=r"((r)[1]), "=r"((r)[2]), "=r"((r)[3]) : "r"(addr))

#define MMA16816(d, a, b0, b1)                                                \
    asm volatile("mma.sync.aligned.m16n8k16.row.col.f32.bf16.bf16.f32 "       \
        "{%0,%1,%2,%3}, {%4,%5,%6,%7}, {%8,%9}, {%0,%1,%2,%3};"               \
        : "+f"((d)[0]), "+f"((d)[1]), "+f"((d)[2]), "+f"((d)[3])              \
        : "r"((a)[0]), "r"((a)[1]), "r"((a)[2]), "r"((a)[3]),                 \
          "r"(b0), "r"(b1))

// ---------------------------------------------------------------------------
// Pack kernels: split-bf16 operands.
//   A_cat[b][k'] = [hi | lo | hi] of (x|h)[b]
//   W_cat[n][k'] = [hi | hi | lo] of W[.][n]  (K-major, transposed)
// ---------------------------------------------------------------------------
__global__ __launch_bounds__(256)
void pack_a_kernel(const float* __restrict__ x, const float* __restrict__ h) {
    const int b = blockIdx.y;
    const int k = blockIdx.x * 256 + threadIdx.x;
    float v = (k < I_DIM) ? x[(size_t)b * I_DIM + k]
                          : h[(size_t)b * H_DIM + (k - I_DIM)];
    __nv_bfloat16 hi = __float2bfloat16(v);
    __nv_bfloat16 lo = __float2bfloat16(v - __bfloat162float(hi));
    const size_t base = (size_t)b * K_EFF;
    g_Acat[base + k]             = hi;
    g_Acat[base + K_RAW + k]     = lo;
    g_Acat[base + 2 * K_RAW + k] = hi;
}

__global__ __launch_bounds__(256)
void pack_w_kernel(const float* __restrict__ Wi, const float* __restrict__ Wh) {
    __shared__ float t[32][33];
    const int k0 = blockIdx.x * 32;
    const int n0 = blockIdx.y * 32;
    const int tx = threadIdx.x, ty = threadIdx.y; // 32 x 8
#pragma unroll
    for (int i = 0; i < 4; ++i) {
        const int k = k0 + ty + i * 8;
        const int n = n0 + tx;
        float v = (k < I_DIM) ? Wi[(size_t)k * N_DIM + n]
                              : Wh[(size_t)(k - I_DIM) * N_DIM + n];
        t[ty + i * 8][tx] = v;
    }
    __syncthreads();
#pragma unroll
    for (int i = 0; i < 4; ++i) {
        const int n = n0 + ty + i * 8;
        const int k = k0 + tx;
        float v = t[tx][ty + i * 8];
        __nv_bfloat16 hi = __float2bfloat16(v);
        __nv_bfloat16 lo = __float2bfloat16(v - __bfloat162float(hi));
        const size_t base = (size_t)n * K_EFF;
        g_Wcat[base + k]             = hi;
        g_Wcat[base + K_RAW + k]     = hi;
        g_Wcat[base + 2 * K_RAW + k] = lo;
    }
}

// ---------------------------------------------------------------------------
// bf16 TN GEMM: gates[M,N] = A_cat[M,K] @ W_cat[N,K]^T
//   CTA 128x128x64, 256 thr, 8 warps (2m x 4n), warp tile 64x32.
//   3-stage cp.async pipeline, XOR-swizzled smem, 2 CTAs/SM.
// ---------------------------------------------------------------------------
#define STAGES 3
#define BK 64
#define TILE_M 128
#define TILE_N 128
#define NK (K_EFF / BK)              // 72
#define STAGE_BYTES 32768            // A 16KB + B 16KB
#define SMEM_BYTES (STAGES * STAGE_BYTES)   // 96 KB -> 2 CTAs/SM

__device__ __forceinline__ void issue_stage(uint32_t sbase, int s,
                                            const __nv_bfloat16* A,
                                            const __nv_bfloat16* W,
                                            int m0, int n0, int k0, int tid) {
    const uint32_t sA = sbase + s * STAGE_BYTES;
    const uint32_t sB = sA + 16384;
#pragma unroll
    for (int i = 0; i < 4; ++i) {
        const int idx = tid + 256 * i;          // 0..1023
        const int row = idx >> 3;               // 0..127
        const int c   = idx & 7;                // 16B chunk
        const uint32_t dst_off = row * 128 + ((c ^ (row & 7)) << 4);
        cp16(sA + dst_off, A + (size_t)(m0 + row) * K_EFF + k0 + c * 8);
        cp16(sB + dst_off, W + (size_t)(n0 + row) * K_EFF + k0 + c * 8);
    }
}

__global__ void __launch_bounds__(256, 2)
gemm_mma_kernel(const __nv_bfloat16* __restrict__ A,
                const __nv_bfloat16* __restrict__ W,
                float* __restrict__ out) {
    extern __shared__ char smem[];
    const uint32_t sbase = smem_u32(smem);

    const int tid  = threadIdx.x;
    const int wid  = tid >> 5;
    const int lane = tid & 31;
    const int warp_m = wid >> 2;     // 0..1  -> 64 rows
    const int warp_n = wid & 3;      // 0..3  -> 32 cols
    const int m0 = blockIdx.y * TILE_M;
    const int n0 = blockIdx.x * TILE_N;

    const int lrow  = (lane & 7) + ((lane >> 3) & 1) * 8;  // 0..15
    const int lhalf = lane >> 4;                           // 0/1 (k chunk)

    float acc[4][4][4];
#pragma unroll
    for (int i = 0; i < 4; ++i)
#pragma unroll
        for (int j = 0; j < 4; ++j)
#pragma unroll
            for (int e = 0; e < 4; ++e) acc[i][j][e] = 0.0f;

    // prologue: stages 0,1
#pragma unroll
    for (int s = 0; s < STAGES - 1; ++s) {
        issue_stage(sbase, s, A, W, m0, n0, s * BK, tid);
        CP_COMMIT();
    }

    int s_cur = 0, s_nxt = STAGES - 1;
    for (int kt = 0; kt < NK; ++kt) {
        CP_WAIT1();
        __syncthreads();

        const int knext = kt + STAGES - 1;
        if (knext < NK)
            issue_stage(sbase, s_nxt, A, W, m0, n0, knext * BK, tid);
        CP_COMMIT();
        if (++s_nxt == STAGES) s_nxt = 0;

        const uint32_t sA = sbase + s_cur * STAGE_BYTES;
        const uint32_t sB = sA + 16384;
        if (++s_cur == STAGES) s_cur = 0;

#pragma unroll
        for (int ks = 0; ks < 4; ++ks) {         // 4 x k16 per BK=64
            uint32_t a[4][4];
#pragma unroll
            for (int im = 0; im < 4; ++im) {
                const int row = warp_m * 64 + im * 16 + lrow;
                const int ch  = ks * 2 + lhalf;
                LDSM_X4(a[im], sA + row * 128 + ((ch ^ (row & 7)) << 4));
            }
            uint32_t b[2][4];
#pragma unroll
            for (int jb = 0; jb < 2; ++jb) {
                const int row = warp_n * 32 + jb * 16 + lrow;
                const int ch  = ks * 2 + lhalf;
                LDSM_X4(b[jb], sB + row * 128 + ((ch ^ (row & 7)) << 4));
            }
#pragma unroll
            for (int im = 0; im < 4; ++im)
#pragma unroll
                for (int jn = 0; jn < 4; ++jn)
                    MMA16816(acc[im][jn], a[im],
                             b[jn >> 1][jn & 1], b[jn >> 1][(jn & 1) + 2]);
        }
        __syncthreads();
    }

    // epilogue: write accumulators
#pragma unroll
    for (int im = 0; im < 4; ++im) {
        const int r0 = m0 + warp_m * 64 + im * 16 + (lane >> 2);
#pragma unroll
        for (int jn = 0; jn < 4; ++jn) {
            const int col = n0 + warp_n * 32 + jn * 8 + (lane & 3) * 2;
            float2 v0 = make_float2(acc[im][jn][0], acc[im][jn][1]);
            float2 v1 = make_float2(acc[im][jn][2], acc[im][jn][3]);
            *(float2*)&out[(size_t)r0 * N_DIM + col]       = v0;
            *(float2*)&out[(size_t)(r0 + 8) * N_DIM + col] = v1;
        }
    }
}

// ---------------------------------------------------------------------------
// LayerNorm (+bias) + LSTM elementwise. One block / batch row; warp = gate.
// ---------------------------------------------------------------------------
__device__ __forceinline__ float sigmoidf_(float x) {
    return 1.0f / (1.0f + expf(-x));
}

__global__ __launch_bounds__(128)
void ln_lstm_kernel(const float* __restrict__ gates,  // [B, 4, H] (no bias)
                    const float* __restrict__ c,      // [B, H]
                    const float* __restrict__ bh,     // [4H]
                    const float* __restrict__ gamma,  // [4, H]
                    const float* __restrict__ beta,   // [4, H]
                    float* __restrict__ h_new,
                    float* __restrict__ c_new) {
    const int b    = blockIdx.x;
    const int wid  = threadIdx.x >> 5;
    const int lane = threadIdx.x & 31;

    __shared__ float sh[4][H_DIM];

    const float* row  = gates + (size_t)b * N_DIM + wid * H_DIM;
    const float* brow = bh + wid * H_DIM;

    float4 v[8];
    float sum = 0.0f, sumsq = 0.0f;
#pragma unroll
    for (int i = 0; i < 8; ++i) {
        const int j = (lane + 32 * i) * 4;
        float4 g  = *(const float4*)&row[j];
        float4 bb = *(const float4*)&brow[j];
        v[i].x = g.x + bb.x; v[i].y = g.y + bb.y;
        v[i].z = g.z + bb.z; v[i].w = g.w + bb.w;
        sum   += v[i].x + v[i].y + v[i].z + v[i].w;
        sumsq += v[i].x * v[i].x + v[i].y * v[i].y
               + v[i].z * v[i].z + v[i].w * v[i].w;
    }
#pragma unroll
    for (int off = 16; off > 0; off >>= 1) {
        sum   += __shfl_xor_sync(0xffffffffu, sum,   off);
        sumsq += __shfl_xor_sync(0xffffffffu, sumsq, off);
    }
    const float inv_n = 1.0f / (float)H_DIM;
    const float mean = sum * inv_n;
    const float var  = fmaxf(sumsq * inv_n - mean * mean, 0.0f);
    const float rstd = rsqrtf(var + 1e-5f);

    const float* gam = gamma + wid * H_DIM;
    const float* bet = beta  + wid * H_DIM;
#pragma unroll
    for (int i = 0; i < 8; ++i) {
        const int j = (lane + 32 * i) * 4;
        float4 gv = *(const float4*)&gam[j];
        float4 bv = *(const float4*)&bet[j];
        float4 y;
        y.x = (v[i].x - mean) * rstd * gv.x + bv.x;
        y.y = (v[i].y - mean) * rstd * gv.y + bv.y;
        y.z = (v[i].z - mean) * rstd * gv.z + bv.z;
        y.w = (v[i].w - mean) * rstd * gv.w + bv.w;
        *(float4*)&sh[wid][j] = y;
    }
    __syncthreads();

    const size_t base = (size_t)b * H_DIM;
#pragma unroll
    for (int ii = 0; ii < 2; ++ii) {
        const int j = (threadIdx.x + 128 * ii) * 4;
        float4 ig = *(const float4*)&sh[0][j];
        float4 fg = *(const float4*)&sh[1][j];
        float4 gg = *(const float4*)&sh[2][j];
        float4 og = *(const float4*)&sh[3][j];
        float4 cv = *(const float4*)&c[base + j];

        float4 cn, hn;
        cn.x = sigmoidf_(fg.x) * cv.x + sigmoidf_(ig.x) * tanhf(gg.x);
        cn.y = sigmoidf_(fg.y) * cv.y + sigmoidf_(ig.y) * tanhf(gg.y);
        cn.z = sigmoidf_(fg.z) * cv.z + sigmoidf_(ig.z) * tanhf(gg.z);
        cn.w = sigmoidf_(fg.w) * cv.w + sigmoidf_(ig.w) * tanhf(gg.w);
        hn.x = sigmoidf_(og.x) * tanhf(cn.x);
        hn.y = sigmoidf_(og.y) * tanhf(cn.y);
        hn.z = sigmoidf_(og.z) * tanhf(cn.z);
        hn.w = sigmoidf_(og.w) * tanhf(cn.w);

        *(float4*)&c_new[base + j] = cn;
        *(float4*)&h_new[base + j] = hn;
    }
}

// ---------------------------------------------------------------------------
// Host launcher
// ---------------------------------------------------------------------------
extern "C" void kernel_launch(void* const* d_in, const int* in_sizes, int n_in,
                              void* d_out, int out_size) {
    const float* x     = (const float*)d_in[0];
    const float* h     = (const float*)d_in[1];
    const float* c     = (const float*)d_in[2];
    const float* Wi    = (const float*)d_in[3];
    const float* Wh    = (const float*)d_in[4];
    const float* bh    = (const float*)d_in[5];
    const float* gamma = (const float*)d_in[6];
    const float* beta  = (const float*)d_in[7];

    float* out   = (float*)d_out;
    float* h_new = out;
    float* c_new = out + (size_t)B_DIM * H_DIM;

    float* gates;         cudaGetSymbolAddress((void**)&gates, g_gates);
    __nv_bfloat16* a_ptr; cudaGetSymbolAddress((void**)&a_ptr, g_Acat);
    __nv_bfloat16* w_ptr; cudaGetSymbolAddress((void**)&w_ptr, g_Wcat);

    pack_a_kernel<<<dim3(K_RAW / 256, B_DIM), 256>>>(x, h);
    pack_w_kernel<<<dim3(K_RAW / 32, N_DIM / 32), dim3(32, 8)>>>(Wi, Wh);

    cudaFuncSetAttribute(gemm_mma_kernel,
                         cudaFuncAttributeMaxDynamicSharedMemorySize, SMEM_BYTES);
    gemm_mma_kernel<<<dim3(N_DIM / TILE_N, B_DIM / TILE_M), 256, SMEM_BYTES>>>(
        a_ptr, w_ptr, gates);

    ln_lstm_kernel<<<B_DIM, 128>>>(gates, c, bh, gamma, beta, h_new, c_new);
}

// round 6
// speedup vs baseline: 2.2331x; 1.4151x over previous
#include <cuda_runtime.h>
#include <cuda_fp16.h>
#include <math.h>
#include <stdint.h>

// ---------------------------------------------------------------------------
// Shapes: B=8192, I=512, H=1024, N=4096, K=1536, K_eff=2*1536=3072
// gates = x@Wi + h@Wh (bias folded into LN); per-gate LayerNorm; LSTM math.
// GEMM numerics: A rounded once to fp16; W split into fp16 hi+lo.
//   gates ~= A_f16 @ W_hi^T + A_f16 @ W_lo^T   (fp32 accumulate)
//   error ~ (A - A_f16)*W ~ 2^-11  -> rel_err ~ 5e-4 < 1e-3.
// Tile 128x128x64, warp tile 64x32, 3-stage cp.async, 2 CTAs/SM.
// ---------------------------------------------------------------------------
#define B_DIM 8192
#define I_DIM 512
#define H_DIM 1024
#define N_DIM 4096
#define K_RAW 1536
#define K_EFF 3072

__device__ float g_gates[(size_t)B_DIM * N_DIM];                   // 128 MB
__device__ __align__(1024) __half g_Ah[(size_t)B_DIM * K_RAW];     // 25 MB
__device__ __align__(1024) __half g_Wcat[(size_t)N_DIM * K_EFF];   // 25 MB

// ------------------------------ PTX helpers --------------------------------
__device__ __forceinline__ uint32_t smem_u32(const void* p) {
    uint32_t a;
    asm("{ .reg .u64 t; cvta.to.shared.u64 t, %1; cvt.u32.u64 %0, t; }"
        : "=r"(a) : "l"(p));
    return a;
}

__device__ __forceinline__ void cp16(uint32_t dst, const void* src) {
    asm volatile("cp.async.cg.shared.global [%0], [%1], 16;"
                 :: "r"(dst), "l"(src) : "memory");
}
#define CP_COMMIT() asm volatile("cp.async.commit_group;" ::: "memory")
#define CP_WAIT1()  asm volatile("cp.async.wait_group 1;"  ::: "memory")

#define LDSM_X4(r, addr)                                                      \
    asm volatile("ldmatrix.sync.aligned.m8n8.x4.shared.b16 {%0,%1,%2,%3}, [%4];" \
        : "=r"((r)[0]), "=r"((r)[1]), "=r"((r)[2]), "=r"((r)[3]) : "r"(addr))

#define MMA16816(d, a, b0, b1)                                                \
    asm volatile("mma.sync.aligned.m16n8k16.row.col.f32.f16.f16.f32 "         \
        "{%0,%1,%2,%3}, {%4,%5,%6,%7}, {%8,%9}, {%0,%1,%2,%3};"               \
        : "+f"((d)[0]), "+f"((d)[1]), "+f"((d)[2]), "+f"((d)[3])              \
        : "r"((a)[0]), "r"((a)[1]), "r"((a)[2]), "r"((a)[3]),                 \
          "r"(b0), "r"(b1))

// ---------------------------------------------------------------------------
// Pack kernels.
//   A_h[b][k]   = fp16( (x|h)[b][k] )                       (K_RAW cols)
//   W_cat[n][k'] = [W_hi | W_lo] of W[.][n], K-major         (K_EFF cols)
// ---------------------------------------------------------------------------
__global__ __launch_bounds__(256)
void pack_a_kernel(const float* __restrict__ x, const float* __restrict__ h) {
    const int b = blockIdx.y;
    const int k = blockIdx.x * 256 + threadIdx.x;
    float v = (k < I_DIM) ? x[(size_t)b * I_DIM + k]
                          : h[(size_t)b * H_DIM + (k - I_DIM)];
    g_Ah[(size_t)b * K_RAW + k] = __float2half(v);
}

__global__ __launch_bounds__(256)
void pack_w_kernel(const float* __restrict__ Wi, const float* __restrict__ Wh) {
    __shared__ float t[32][33];
    const int k0 = blockIdx.x * 32;
    const int n0 = blockIdx.y * 32;
    const int tx = threadIdx.x, ty = threadIdx.y; // 32 x 8
#pragma unroll
    for (int i = 0; i < 4; ++i) {
        const int k = k0 + ty + i * 8;
        const int n = n0 + tx;
        float v = (k < I_DIM) ? Wi[(size_t)k * N_DIM + n]
                              : Wh[(size_t)(k - I_DIM) * N_DIM + n];
        t[ty + i * 8][tx] = v;
    }
    __syncthreads();
#pragma unroll
    for (int i = 0; i < 4; ++i) {
        const int n = n0 + ty + i * 8;
        const int k = k0 + tx;
        float v = t[tx][ty + i * 8];
        __half hi = __float2half(v);
        __half lo = __float2half(v - __half2float(hi));
        const size_t base = (size_t)n * K_EFF;
        g_Wcat[base + k]         = hi;
        g_Wcat[base + K_RAW + k] = lo;
    }
}

// ---------------------------------------------------------------------------
// fp16 TN GEMM: gates[M,N] = A_h[M, k mod K_RAW] @ W_cat[N, K_EFF]^T
//   CTA 128x128x64, 256 thr, 8 warps (2m x 4n), warp tile 64x32.
//   3-stage cp.async pipeline, XOR-swizzled smem, 2 CTAs/SM.
// ---------------------------------------------------------------------------
#define STAGES 3
#define BK 64
#define TILE_M 128
#define TILE_N 128
#define NK (K_EFF / BK)              // 48
#define STAGE_BYTES 32768            // A 16KB + B 16KB
#define SMEM_BYTES (STAGES * STAGE_BYTES)   // 96 KB -> 2 CTAs/SM

__device__ __forceinline__ void issue_stage(uint32_t sbase, int s,
                                            const __half* A,
                                            const __half* W,
                                            int m0, int n0, int k0, int tid) {
    const uint32_t sA = sbase + s * STAGE_BYTES;
    const uint32_t sB = sA + 16384;
    const int k0a = k0 % K_RAW;      // A wraps: same A for hi and lo W terms
#pragma unroll
    for (int i = 0; i < 4; ++i) {
        const int idx = tid + 256 * i;          // 0..1023
        const int row = idx >> 3;               // 0..127
        const int c   = idx & 7;                // 16B chunk
        const uint32_t dst_off = row * 128 + ((c ^ (row & 7)) << 4);
        cp16(sA + dst_off, A + (size_t)(m0 + row) * K_RAW + k0a + c * 8);
        cp16(sB + dst_off, W + (size_t)(n0 + row) * K_EFF + k0 + c * 8);
    }
}

__global__ void __launch_bounds__(256, 2)
gemm_mma_kernel(const __half* __restrict__ A,
                const __half* __restrict__ W,
                float* __restrict__ out) {
    extern __shared__ char smem[];
    const uint32_t sbase = smem_u32(smem);

    const int tid  = threadIdx.x;
    const int wid  = tid >> 5;
    const int lane = tid & 31;
    const int warp_m = wid >> 2;     // 0..1  -> 64 rows
    const int warp_n = wid & 3;      // 0..3  -> 32 cols
    const int m0 = blockIdx.y * TILE_M;
    const int n0 = blockIdx.x * TILE_N;

    const int lrow  = (lane & 7) + ((lane >> 3) & 1) * 8;  // 0..15
    const int lhalf = lane >> 4;                           // 0/1 (k chunk)

    float acc[4][4][4];
#pragma unroll
    for (int i = 0; i < 4; ++i)
#pragma unroll
        for (int j = 0; j < 4; ++j)
#pragma unroll
            for (int e = 0; e < 4; ++e) acc[i][j][e] = 0.0f;

    // prologue: stages 0,1
#pragma unroll
    for (int s = 0; s < STAGES - 1; ++s) {
        issue_stage(sbase, s, A, W, m0, n0, s * BK, tid);
        CP_COMMIT();
    }

    int s_cur = 0, s_nxt = STAGES - 1;
    for (int kt = 0; kt < NK; ++kt) {
        CP_WAIT1();
        __syncthreads();
        // Single barrier per iteration: this barrier orders iteration kt-1's
        // smem reads (all warps) before the cp.async writes below, which
        // target stage (kt+2)%3 == (kt-1)%3 at the NEXT iteration's issue.

        const int knext = kt + STAGES - 1;
        if (knext < NK)
            issue_stage(sbase, s_nxt, A, W, m0, n0, knext * BK, tid);
        CP_COMMIT();
        if (++s_nxt == STAGES) s_nxt = 0;

        const uint32_t sA = sbase + s_cur * STAGE_BYTES;
        const uint32_t sB = sA + 16384;
        if (++s_cur == STAGES) s_cur = 0;

#pragma unroll
        for (int ks = 0; ks < 4; ++ks) {         // 4 x k16 per BK=64
            uint32_t a[4][4];
#pragma unroll
            for (int im = 0; im < 4; ++im) {
                const int row = warp_m * 64 + im * 16 + lrow;
                const int ch  = ks * 2 + lhalf;
                LDSM_X4(a[im], sA + row * 128 + ((ch ^ (row & 7)) << 4));
            }
            uint32_t b[2][4];
#pragma unroll
            for (int jb = 0; jb < 2; ++jb) {
                const int row = warp_n * 32 + jb * 16 + lrow;
                const int ch  = ks * 2 + lhalf;
                LDSM_X4(b[jb], sB + row * 128 + ((ch ^ (row & 7)) << 4));
            }
#pragma unroll
            for (int im = 0; im < 4; ++im)
#pragma unroll
                for (int jn = 0; jn < 4; ++jn)
                    MMA16816(acc[im][jn], a[im],
                             b[jn >> 1][jn & 1], b[jn >> 1][(jn & 1) + 2]);
        }
    }

    // epilogue: write accumulators
#pragma unroll
    for (int im = 0; im < 4; ++im) {
        const int r0 = m0 + warp_m * 64 + im * 16 + (lane >> 2);
#pragma unroll
        for (int jn = 0; jn < 4; ++jn) {
            const int col = n0 + warp_n * 32 + jn * 8 + (lane & 3) * 2;
            float2 v0 = make_float2(acc[im][jn][0], acc[im][jn][1]);
            float2 v1 = make_float2(acc[im][jn][2], acc[im][jn][3]);
            *(float2*)&out[(size_t)r0 * N_DIM + col]       = v0;
            *(float2*)&out[(size_t)(r0 + 8) * N_DIM + col] = v1;
        }
    }
}

// ---------------------------------------------------------------------------
// LayerNorm (+bias) + LSTM elementwise. One block / batch row; warp = gate.
// ---------------------------------------------------------------------------
__device__ __forceinline__ float sigmoidf_(float x) {
    return 1.0f / (1.0f + expf(-x));
}

__global__ __launch_bounds__(128)
void ln_lstm_kernel(const float* __restrict__ gates,  // [B, 4, H] (no bias)
                    const float* __restrict__ c,      // [B, H]
                    const float* __restrict__ bh,     // [4H]
                    const float* __restrict__ gamma,  // [4, H]
                    const float* __restrict__ beta,   // [4, H]
                    float* __restrict__ h_new,
                    float* __restrict__ c_new) {
    const int b    = blockIdx.x;
    const int wid  = threadIdx.x >> 5;
    const int lane = threadIdx.x & 31;

    __shared__ float sh[4][H_DIM];

    const float* row  = gates + (size_t)b * N_DIM + wid * H_DIM;
    const float* brow = bh + wid * H_DIM;

    float4 v[8];
    float sum = 0.0f, sumsq = 0.0f;
#pragma unroll
    for (int i = 0; i < 8; ++i) {
        const int j = (lane + 32 * i) * 4;
        float4 g  = *(const float4*)&row[j];
        float4 bb = *(const float4*)&brow[j];
        v[i].x = g.x + bb.x; v[i].y = g.y + bb.y;
        v[i].z = g.z + bb.z; v[i].w = g.w + bb.w;
        sum   += v[i].x + v[i].y + v[i].z + v[i].w;
        sumsq += v[i].x * v[i].x + v[i].y * v[i].y
               + v[i].z * v[i].z + v[i].w * v[i].w;
    }
#pragma unroll
    for (int off = 16; off > 0; off >>= 1) {
        sum   += __shfl_xor_sync(0xffffffffu, sum,   off);
        sumsq += __shfl_xor_sync(0xffffffffu, sumsq, off);
    }
    const float inv_n = 1.0f / (float)H_DIM;
    const float mean = sum * inv_n;
    const float var  = fmaxf(sumsq * inv_n - mean * mean, 0.0f);
    const float rstd = rsqrtf(var + 1e-5f);

    const float* gam = gamma + wid * H_DIM;
    const float* bet = beta  + wid * H_DIM;
#pragma unroll
    for (int i = 0; i < 8; ++i) {
        const int j = (lane + 32 * i) * 4;
        float4 gv = *(const float4*)&gam[j];
        float4 bv = *(const float4*)&bet[j];
        float4 y;
        y.x = (v[i].x - mean) * rstd * gv.x + bv.x;
        y.y = (v[i].y - mean) * rstd * gv.y + bv.y;
        y.z = (v[i].z - mean) * rstd * gv.z + bv.z;
        y.w = (v[i].w - mean) * rstd * gv.w + bv.w;
        *(float4*)&sh[wid][j] = y;
    }
    __syncthreads();

    const size_t base = (size_t)b * H_DIM;
#pragma unroll
    for (int ii = 0; ii < 2; ++ii) {
        const int j = (threadIdx.x + 128 * ii) * 4;
        float4 ig = *(const float4*)&sh[0][j];
        float4 fg = *(const float4*)&sh[1][j];
        float4 gg = *(const float4*)&sh[2][j];
        float4 og = *(const float4*)&sh[3][j];
        float4 cv = *(const float4*)&c[base + j];

        float4 cn, hn;
        cn.x = sigmoidf_(fg.x) * cv.x + sigmoidf_(ig.x) * tanhf(gg.x);
        cn.y = sigmoidf_(fg.y) * cv.y + sigmoidf_(ig.y) * tanhf(gg.y);
        cn.z = sigmoidf_(fg.z) * cv.z + sigmoidf_(ig.z) * tanhf(gg.z);
        cn.w = sigmoidf_(fg.w) * cv.w + sigmoidf_(ig.w) * tanhf(gg.w);
        hn.x = sigmoidf_(og.x) * tanhf(cn.x);
        hn.y = sigmoidf_(og.y) * tanhf(cn.y);
        hn.z = sigmoidf_(og.z) * tanhf(cn.z);
        hn.w = sigmoidf_(og.w) * tanhf(cn.w);

        *(float4*)&c_new[base + j] = cn;
        *(float4*)&h_new[base + j] = hn;
    }
}

// ---------------------------------------------------------------------------
// Host launcher
// ---------------------------------------------------------------------------
extern "C" void kernel_launch(void* const* d_in, const int* in_sizes, int n_in,
                              void* d_out, int out_size) {
    const float* x     = (const float*)d_in[0];
    const float* h     = (const float*)d_in[1];
    const float* c     = (const float*)d_in[2];
    const float* Wi    = (const float*)d_in[3];
    const float* Wh    = (const float*)d_in[4];
    const float* bh    = (const float*)d_in[5];
    const float* gamma = (const float*)d_in[6];
    const float* beta  = (const float*)d_in[7];

    float* out   = (float*)d_out;
    float* h_new = out;
    float* c_new = out + (size_t)B_DIM * H_DIM;

    float* gates;  cudaGetSymbolAddress((void**)&gates, g_gates);
    __half* a_ptr; cudaGetSymbolAddress((void**)&a_ptr, g_Ah);
    __half* w_ptr; cudaGetSymbolAddress((void**)&w_ptr, g_Wcat);

    pack_a_kernel<<<dim3(K_RAW / 256, B_DIM), 256>>>(x, h);
    pack_w_kernel<<<dim3(K_RAW / 32, N_DIM / 32), dim3(32, 8)>>>(Wi, Wh);

    cudaFuncSetAttribute(gemm_mma_kernel,
                         cudaFuncAttributeMaxDynamicSharedMemorySize, SMEM_BYTES);
    gemm_mma_kernel<<<dim3(N_DIM / TILE_N, B_DIM / TILE_M), 256, SMEM_BYTES>>>(
        a_ptr, w_ptr, gates);

    ln_lstm_kernel<<<B_DIM, 128>>>(gates, c, bh, gamma, beta, h_new, c_new);
}

// round 7
// speedup vs baseline: 3.7628x; 1.6850x over previous
#include <cuda_runtime.h>
#include <cuda_fp16.h>
#include <math.h>
#include <stdint.h>

// ---------------------------------------------------------------------------
// Shapes: B=8192, I=512, H=1024, N=4096, K=1536
// gates = x@Wi + h@Wh (bias folded into LN); per-gate LayerNorm; LSTM math.
// GEMM numerics: BOTH A and W rounded once to fp16, fp32 accumulate.
//   error ~ (A-A16)W + A(W-W16) ~ 2^-11 class, stochastic accumulation;
//   measured 1.7e-4 with A-only rounding -> expect ~2.5-3.5e-4 here.
// Tile 128x128x64, warp tile 64x32, 3-stage cp.async, 2 CTAs/SM.
// ---------------------------------------------------------------------------
#define B_DIM 8192
#define I_DIM 512
#define H_DIM 1024
#define N_DIM 4096
#define K_RAW 1536

__device__ float g_gates[(size_t)B_DIM * N_DIM];                   // 128 MB
__device__ __align__(1024) __half g_Ah[(size_t)B_DIM * K_RAW];     // 25 MB
__device__ __align__(1024) __half g_Wh[(size_t)N_DIM * K_RAW];     // 12.5 MB

// ------------------------------ PTX helpers --------------------------------
__device__ __forceinline__ uint32_t smem_u32(const void* p) {
    uint32_t a;
    asm("{ .reg .u64 t; cvta.to.shared.u64 t, %1; cvt.u32.u64 %0, t; }"
        : "=r"(a) : "l"(p));
    return a;
}

__device__ __forceinline__ void cp16(uint32_t dst, const void* src) {
    asm volatile("cp.async.cg.shared.global [%0], [%1], 16;"
                 :: "r"(dst), "l"(src) : "memory");
}
#define CP_COMMIT() asm volatile("cp.async.commit_group;" ::: "memory")
#define CP_WAIT1()  asm volatile("cp.async.wait_group 1;"  ::: "memory")

#define LDSM_X4(r, addr)                                                      \
    asm volatile("ldmatrix.sync.aligned.m8n8.x4.shared.b16 {%0,%1,%2,%3}, [%4];" \
        : "=r"((r)[0]), "=r"((r)[1]), "=r"((r)[2]), "=r"((r)[3]) : "r"(addr))

#define MMA16816(d, a, b0, b1)                                                \
    asm volatile("mma.sync.aligned.m16n8k16.row.col.f32.f16.f16.f32 "         \
        "{%0,%1,%2,%3}, {%4,%5,%6,%7}, {%8,%9}, {%0,%1,%2,%3};"               \
        : "+f"((d)[0]), "+f"((d)[1]), "+f"((d)[2]), "+f"((d)[3])              \
        : "r"((a)[0]), "r"((a)[1]), "r"((a)[2]), "r"((a)[3]),                 \
          "r"(b0), "r"(b1))

// ---------------------------------------------------------------------------
// Pack kernels.
//   A_h[b][k] = fp16( (x|h)[b][k] )
//   W_h[n][k] = fp16( W[k][n] )  (K-major, transposed)
// ---------------------------------------------------------------------------
__global__ __launch_bounds__(256)
void pack_a_kernel(const float* __restrict__ x, const float* __restrict__ h) {
    const int b = blockIdx.y;
    const int k = blockIdx.x * 256 + threadIdx.x;
    float v = (k < I_DIM) ? x[(size_t)b * I_DIM + k]
                          : h[(size_t)b * H_DIM + (k - I_DIM)];
    g_Ah[(size_t)b * K_RAW + k] = __float2half(v);
}

__global__ __launch_bounds__(256)
void pack_w_kernel(const float* __restrict__ Wi, const float* __restrict__ Wh) {
    __shared__ float t[32][33];
    const int k0 = blockIdx.x * 32;
    const int n0 = blockIdx.y * 32;
    const int tx = threadIdx.x, ty = threadIdx.y; // 32 x 8
#pragma unroll
    for (int i = 0; i < 4; ++i) {
        const int k = k0 + ty + i * 8;
        const int n = n0 + tx;
        float v = (k < I_DIM) ? Wi[(size_t)k * N_DIM + n]
                              : Wh[(size_t)(k - I_DIM) * N_DIM + n];
        t[ty + i * 8][tx] = v;
    }
    __syncthreads();
#pragma unroll
    for (int i = 0; i < 4; ++i) {
        const int n = n0 + ty + i * 8;
        const int k = k0 + tx;
        g_Wh[(size_t)n * K_RAW + k] = __float2half(t[tx][ty + i * 8]);
    }
}

// ---------------------------------------------------------------------------
// fp16 TN GEMM: gates[M,N] = A_h[M,K] @ W_h[N,K]^T
//   CTA 128x128x64, 256 thr, 8 warps (2m x 4n), warp tile 64x32.
//   3-stage cp.async pipeline, XOR-swizzled smem, 2 CTAs/SM.
// ---------------------------------------------------------------------------
#define STAGES 3
#define BK 64
#define TILE_M 128
#define TILE_N 128
#define NK (K_RAW / BK)              // 24
#define STAGE_BYTES 32768            // A 16KB + B 16KB
#define SMEM_BYTES (STAGES * STAGE_BYTES)   // 96 KB -> 2 CTAs/SM

__device__ __forceinline__ void issue_stage(uint32_t sbase, int s,
                                            const __half* A,
                                            const __half* W,
                                            int m0, int n0, int k0, int tid) {
    const uint32_t sA = sbase + s * STAGE_BYTES;
    const uint32_t sB = sA + 16384;
#pragma unroll
    for (int i = 0; i < 4; ++i) {
        const int idx = tid + 256 * i;          // 0..1023
        const int row = idx >> 3;               // 0..127
        const int c   = idx & 7;                // 16B chunk
        const uint32_t dst_off = row * 128 + ((c ^ (row & 7)) << 4);
        cp16(sA + dst_off, A + (size_t)(m0 + row) * K_RAW + k0 + c * 8);
        cp16(sB + dst_off, W + (size_t)(n0 + row) * K_RAW + k0 + c * 8);
    }
}

__global__ void __launch_bounds__(256, 2)
gemm_mma_kernel(const __half* __restrict__ A,
                const __half* __restrict__ W,
                float* __restrict__ out) {
    extern __shared__ char smem[];
    const uint32_t sbase = smem_u32(smem);

    const int tid  = threadIdx.x;
    const int wid  = tid >> 5;
    const int lane = tid & 31;
    const int warp_m = wid >> 2;     // 0..1  -> 64 rows
    const int warp_n = wid & 3;      // 0..3  -> 32 cols
    const int m0 = blockIdx.y * TILE_M;
    const int n0 = blockIdx.x * TILE_N;

    const int lrow  = (lane & 7) + ((lane >> 3) & 1) * 8;  // 0..15
    const int lhalf = lane >> 4;                           // 0/1 (k chunk)

    float acc[4][4][4];
#pragma unroll
    for (int i = 0; i < 4; ++i)
#pragma unroll
        for (int j = 0; j < 4; ++j)
#pragma unroll
            for (int e = 0; e < 4; ++e) acc[i][j][e] = 0.0f;

    // prologue: stages 0,1
#pragma unroll
    for (int s = 0; s < STAGES - 1; ++s) {
        issue_stage(sbase, s, A, W, m0, n0, s * BK, tid);
        CP_COMMIT();
    }

    int s_cur = 0, s_nxt = STAGES - 1;
    for (int kt = 0; kt < NK; ++kt) {
        CP_WAIT1();
        __syncthreads();
        // Single barrier per iteration: orders iteration kt-1's smem reads
        // before the cp.async writes below (which target that stage).

        const int knext = kt + STAGES - 1;
        if (knext < NK)
            issue_stage(sbase, s_nxt, A, W, m0, n0, knext * BK, tid);
        CP_COMMIT();
        if (++s_nxt == STAGES) s_nxt = 0;

        const uint32_t sA = sbase + s_cur * STAGE_BYTES;
        const uint32_t sB = sA + 16384;
        if (++s_cur == STAGES) s_cur = 0;

#pragma unroll
        for (int ks = 0; ks < 4; ++ks) {         // 4 x k16 per BK=64
            uint32_t a[4][4];
#pragma unroll
            for (int im = 0; im < 4; ++im) {
                const int row = warp_m * 64 + im * 16 + lrow;
                const int ch  = ks * 2 + lhalf;
                LDSM_X4(a[im], sA + row * 128 + ((ch ^ (row & 7)) << 4));
            }
            uint32_t b[2][4];
#pragma unroll
            for (int jb = 0; jb < 2; ++jb) {
                const int row = warp_n * 32 + jb * 16 + lrow;
                const int ch  = ks * 2 + lhalf;
                LDSM_X4(b[jb], sB + row * 128 + ((ch ^ (row & 7)) << 4));
            }
#pragma unroll
            for (int im = 0; im < 4; ++im)
#pragma unroll
                for (int jn = 0; jn < 4; ++jn)
                    MMA16816(acc[im][jn], a[im],
                             b[jn >> 1][jn & 1], b[jn >> 1][(jn & 1) + 2]);
        }
    }

    // epilogue: write accumulators
#pragma unroll
    for (int im = 0; im < 4; ++im) {
        const int r0 = m0 + warp_m * 64 + im * 16 + (lane >> 2);
#pragma unroll
        for (int jn = 0; jn < 4; ++jn) {
            const int col = n0 + warp_n * 32 + jn * 8 + (lane & 3) * 2;
            float2 v0 = make_float2(acc[im][jn][0], acc[im][jn][1]);
            float2 v1 = make_float2(acc[im][jn][2], acc[im][jn][3]);
            *(float2*)&out[(size_t)r0 * N_DIM + col]       = v0;
            *(float2*)&out[(size_t)(r0 + 8) * N_DIM + col] = v1;
        }
    }
}

// ---------------------------------------------------------------------------
// LayerNorm (+bias) + LSTM elementwise. One block / batch row; warp = gate.
// ---------------------------------------------------------------------------
__device__ __forceinline__ float sigmoidf_(float x) {
    return 1.0f / (1.0f + expf(-x));
}

__global__ __launch_bounds__(128)
void ln_lstm_kernel(const float* __restrict__ gates,  // [B, 4, H] (no bias)
                    const float* __restrict__ c,      // [B, H]
                    const float* __restrict__ bh,     // [4H]
                    const float* __restrict__ gamma,  // [4, H]
                    const float* __restrict__ beta,   // [4, H]
                    float* __restrict__ h_new,
                    float* __restrict__ c_new) {
    const int b    = blockIdx.x;
    const int wid  = threadIdx.x >> 5;
    const int lane = threadIdx.x & 31;

    __shared__ float sh[4][H_DIM];

    const float* row  = gates + (size_t)b * N_DIM + wid * H_DIM;
    const float* brow = bh + wid * H_DIM;

    float4 v[8];
    float sum = 0.0f, sumsq = 0.0f;
#pragma unroll
    for (int i = 0; i < 8; ++i) {
        const int j = (lane + 32 * i) * 4;
        float4 g  = *(const float4*)&row[j];
        float4 bb = *(const float4*)&brow[j];
        v[i].x = g.x + bb.x; v[i].y = g.y + bb.y;
        v[i].z = g.z + bb.z; v[i].w = g.w + bb.w;
        sum   += v[i].x + v[i].y + v[i].z + v[i].w;
        sumsq += v[i].x * v[i].x + v[i].y * v[i].y
               + v[i].z * v[i].z + v[i].w * v[i].w;
    }
#pragma unroll
    for (int off = 16; off > 0; off >>= 1) {
        sum   += __shfl_xor_sync(0xffffffffu, sum,   off);
        sumsq += __shfl_xor_sync(0xffffffffu, sumsq, off);
    }
    const float inv_n = 1.0f / (float)H_DIM;
    const float mean = sum * inv_n;
    const float var  = fmaxf(sumsq * inv_n - mean * mean, 0.0f);
    const float rstd = rsqrtf(var + 1e-5f);

    const float* gam = gamma + wid * H_DIM;
    const float* bet = beta  + wid * H_DIM;
#pragma unroll
    for (int i = 0; i < 8; ++i) {
        const int j = (lane + 32 * i) * 4;
        float4 gv = *(const float4*)&gam[j];
        float4 bv = *(const float4*)&bet[j];
        float4 y;
        y.x = (v[i].x - mean) * rstd * gv.x + bv.x;
        y.y = (v[i].y - mean) * rstd * gv.y + bv.y;
        y.z = (v[i].z - mean) * rstd * gv.z + bv.z;
        y.w = (v[i].w - mean) * rstd * gv.w + bv.w;
        *(float4*)&sh[wid][j] = y;
    }
    __syncthreads();

    const size_t base = (size_t)b * H_DIM;
#pragma unroll
    for (int ii = 0; ii < 2; ++ii) {
        const int j = (threadIdx.x + 128 * ii) * 4;
        float4 ig = *(const float4*)&sh[0][j];
        float4 fg = *(const float4*)&sh[1][j];
        float4 gg = *(const float4*)&sh[2][j];
        float4 og = *(const float4*)&sh[3][j];
        float4 cv = *(const float4*)&c[base + j];

        float4 cn, hn;
        cn.x = sigmoidf_(fg.x) * cv.x + sigmoidf_(ig.x) * tanhf(gg.x);
        cn.y = sigmoidf_(fg.y) * cv.y + sigmoidf_(ig.y) * tanhf(gg.y);
        cn.z = sigmoidf_(fg.z) * cv.z + sigmoidf_(ig.z) * tanhf(gg.z);
        cn.w = sigmoidf_(fg.w) * cv.w + sigmoidf_(ig.w) * tanhf(gg.w);
        hn.x = sigmoidf_(og.x) * tanhf(cn.x);
        hn.y = sigmoidf_(og.y) * tanhf(cn.y);
        hn.z = sigmoidf_(og.z) * tanhf(cn.z);
        hn.w = sigmoidf_(og.w) * tanhf(cn.w);

        *(float4*)&c_new[base + j] = cn;
        *(float4*)&h_new[base + j] = hn;
    }
}

// ---------------------------------------------------------------------------
// Host launcher
// ---------------------------------------------------------------------------
extern "C" void kernel_launch(void* const* d_in, const int* in_sizes, int n_in,
                              void* d_out, int out_size) {
    const float* x     = (const float*)d_in[0];
    const float* h     = (const float*)d_in[1];
    const float* c     = (const float*)d_in[2];
    const float* Wi    = (const float*)d_in[3];
    const float* Wh    = (const float*)d_in[4];
    const float* bh    = (const float*)d_in[5];
    const float* gamma = (const float*)d_in[6];
    const float* beta  = (const float*)d_in[7];

    float* out   = (float*)d_out;
    float* h_new = out;
    float* c_new = out + (size_t)B_DIM * H_DIM;

    float* gates;  cudaGetSymbolAddress((void**)&gates, g_gates);
    __half* a_ptr; cudaGetSymbolAddress((void**)&a_ptr, g_Ah);
    __half* w_ptr; cudaGetSymbolAddress((void**)&w_ptr, g_Wh);

    pack_a_kernel<<<dim3(K_RAW / 256, B_DIM), 256>>>(x, h);
    pack_w_kernel<<<dim3(K_RAW / 32, N_DIM / 32), dim3(32, 8)>>>(Wi, Wh);

    cudaFuncSetAttribute(gemm_mma_kernel,
                         cudaFuncAttributeMaxDynamicSharedMemorySize, SMEM_BYTES);
    gemm_mma_kernel<<<dim3(N_DIM / TILE_N, B_DIM / TILE_M), 256, SMEM_BYTES>>>(
        a_ptr, w_ptr, gates);

    ln_lstm_kernel<<<B_DIM, 128>>>(gates, c, bh, gamma, beta, h_new, c_new);
}

// round 8
// speedup vs baseline: 4.0265x; 1.0701x over previous
#include <cuda_runtime.h>
#include <cuda_fp16.h>
#include <math.h>
#include <stdint.h>

// ---------------------------------------------------------------------------
// Shapes: B=8192, I=512, H=1024, N=4096, K=1536
// gates = x@Wi + h@Wh (bias folded into LN); per-gate LayerNorm; LSTM math.
// GEMM: plain fp16 mma.sync (A and W rounded once), fp32 accumulate.
// gates stored as fp16 (unit-variance values; adds one ~2^-11 rounding).
// ---------------------------------------------------------------------------
#define B_DIM 8192
#define I_DIM 512
#define H_DIM 1024
#define N_DIM 4096
#define K_RAW 1536

__device__ __align__(1024) __half g_gates[(size_t)B_DIM * N_DIM];  // 64 MB
__device__ __align__(1024) __half g_Ah[(size_t)B_DIM * K_RAW];     // 25 MB
__device__ __align__(1024) __half g_Wh[(size_t)N_DIM * K_RAW];     // 12.5 MB

// ------------------------------ PTX helpers --------------------------------
__device__ __forceinline__ uint32_t smem_u32(const void* p) {
    uint32_t a;
    asm("{ .reg .u64 t; cvta.to.shared.u64 t, %1; cvt.u32.u64 %0, t; }"
        : "=r"(a) : "l"(p));
    return a;
}

__device__ __forceinline__ void cp16(uint32_t dst, const void* src) {
    asm volatile("cp.async.cg.shared.global [%0], [%1], 16;"
                 :: "r"(dst), "l"(src) : "memory");
}
#define CP_COMMIT() asm volatile("cp.async.commit_group;" ::: "memory")
#define CP_WAIT1()  asm volatile("cp.async.wait_group 1;"  ::: "memory")

#define LDSM_X4(r, addr)                                                      \
    asm volatile("ldmatrix.sync.aligned.m8n8.x4.shared.b16 {%0,%1,%2,%3}, [%4];" \
        : "=r"((r)[0]), "=r"((r)[1]), "=r"((r)[2]), "=r"((r)[3]) : "r"(addr))

#define MMA16816(d, a, b0, b1)                                                \
    asm volatile("mma.sync.aligned.m16n8k16.row.col.f32.f16.f16.f32 "         \
        "{%0,%1,%2,%3}, {%4,%5,%6,%7}, {%8,%9}, {%0,%1,%2,%3};"               \
        : "+f"((d)[0]), "+f"((d)[1]), "+f"((d)[2]), "+f"((d)[3])              \
        : "r"((a)[0]), "r"((a)[1]), "r"((a)[2]), "r"((a)[3]),                 \
          "r"(b0), "r"(b1))

// ---------------------------------------------------------------------------
// Pack kernels.
// ---------------------------------------------------------------------------
__global__ __launch_bounds__(128)
void pack_a_kernel(const float* __restrict__ x, const float* __restrict__ h) {
    const int b  = blockIdx.y;
    const int k4 = (blockIdx.x * 128 + threadIdx.x) * 4;   // grid.x=3 -> 1536
    float4 v = (k4 < I_DIM)
        ? *(const float4*)&x[(size_t)b * I_DIM + k4]
        : *(const float4*)&h[(size_t)b * H_DIM + (k4 - I_DIM)];
    __half2 p0 = __floats2half2_rn(v.x, v.y);
    __half2 p1 = __floats2half2_rn(v.z, v.w);
    *(__half2*)&g_Ah[(size_t)b * K_RAW + k4]     = p0;
    *(__half2*)&g_Ah[(size_t)b * K_RAW + k4 + 2] = p1;
}

__global__ __launch_bounds__(256)
void pack_w_kernel(const float* __restrict__ Wi, const float* __restrict__ Wh) {
    __shared__ float t[32][33];
    const int k0 = blockIdx.x * 32;
    const int n0 = blockIdx.y * 32;
    const int tx = threadIdx.x, ty = threadIdx.y; // 32 x 8
#pragma unroll
    for (int i = 0; i < 4; ++i) {
        const int k = k0 + ty + i * 8;
        const int n = n0 + tx;
        float v = (k < I_DIM) ? Wi[(size_t)k * N_DIM + n]
                              : Wh[(size_t)(k - I_DIM) * N_DIM + n];
        t[ty + i * 8][tx] = v;
    }
    __syncthreads();
#pragma unroll
    for (int i = 0; i < 4; ++i) {
        const int n = n0 + ty + i * 8;
        const int k = k0 + tx;
        g_Wh[(size_t)n * K_RAW + k] = __float2half(t[tx][ty + i * 8]);
    }
}

// ---------------------------------------------------------------------------
// fp16 TN GEMM: gates[M,N] = A_h[M,K] @ W_h[N,K]^T   (fp16 output)
//   CTA 128x128x64, 256 thr, 8 warps (2m x 4n), warp tile 64x32.
//   3-stage cp.async pipeline, XOR-swizzled smem, 2 CTAs/SM.
// ---------------------------------------------------------------------------
#define STAGES 3
#define BK 64
#define TILE_M 128
#define TILE_N 128
#define NK (K_RAW / BK)              // 24
#define STAGE_BYTES 32768            // A 16KB + B 16KB
#define SMEM_BYTES (STAGES * STAGE_BYTES)   // 96 KB -> 2 CTAs/SM

__device__ __forceinline__ void issue_stage(uint32_t sbase, int s,
                                            const __half* A,
                                            const __half* W,
                                            int m0, int n0, int k0, int tid) {
    const uint32_t sA = sbase + s * STAGE_BYTES;
    const uint32_t sB = sA + 16384;
#pragma unroll
    for (int i = 0; i < 4; ++i) {
        const int idx = tid + 256 * i;          // 0..1023
        const int row = idx >> 3;               // 0..127
        const int c   = idx & 7;                // 16B chunk
        const uint32_t dst_off = row * 128 + ((c ^ (row & 7)) << 4);
        cp16(sA + dst_off, A + (size_t)(m0 + row) * K_RAW + k0 + c * 8);
        cp16(sB + dst_off, W + (size_t)(n0 + row) * K_RAW + k0 + c * 8);
    }
}

__global__ void __launch_bounds__(256, 2)
gemm_mma_kernel(const __half* __restrict__ A,
                const __half* __restrict__ W,
                __half* __restrict__ out) {
    extern __shared__ char smem[];
    const uint32_t sbase = smem_u32(smem);

    const int tid  = threadIdx.x;
    const int wid  = tid >> 5;
    const int lane = tid & 31;
    const int warp_m = wid >> 2;     // 0..1  -> 64 rows
    const int warp_n = wid & 3;      // 0..3  -> 32 cols
    const int m0 = blockIdx.y * TILE_M;
    const int n0 = blockIdx.x * TILE_N;

    const int lrow  = (lane & 7) + ((lane >> 3) & 1) * 8;  // 0..15
    const int lhalf = lane >> 4;                           // 0/1 (k chunk)

    float acc[4][4][4];
#pragma unroll
    for (int i = 0; i < 4; ++i)
#pragma unroll
        for (int j = 0; j < 4; ++j)
#pragma unroll
            for (int e = 0; e < 4; ++e) acc[i][j][e] = 0.0f;

#pragma unroll
    for (int s = 0; s < STAGES - 1; ++s) {
        issue_stage(sbase, s, A, W, m0, n0, s * BK, tid);
        CP_COMMIT();
    }

    int s_cur = 0, s_nxt = STAGES - 1;
    for (int kt = 0; kt < NK; ++kt) {
        CP_WAIT1();
        __syncthreads();

        const int knext = kt + STAGES - 1;
        if (knext < NK)
            issue_stage(sbase, s_nxt, A, W, m0, n0, knext * BK, tid);
        CP_COMMIT();
        if (++s_nxt == STAGES) s_nxt = 0;

        const uint32_t sA = sbase + s_cur * STAGE_BYTES;
        const uint32_t sB = sA + 16384;
        if (++s_cur == STAGES) s_cur = 0;

#pragma unroll
        for (int ks = 0; ks < 4; ++ks) {         // 4 x k16 per BK=64
            uint32_t a[4][4];
#pragma unroll
            for (int im = 0; im < 4; ++im) {
                const int row = warp_m * 64 + im * 16 + lrow;
                const int ch  = ks * 2 + lhalf;
                LDSM_X4(a[im], sA + row * 128 + ((ch ^ (row & 7)) << 4));
            }
            uint32_t b[2][4];
#pragma unroll
            for (int jb = 0; jb < 2; ++jb) {
                const int row = warp_n * 32 + jb * 16 + lrow;
                const int ch  = ks * 2 + lhalf;
                LDSM_X4(b[jb], sB + row * 128 + ((ch ^ (row & 7)) << 4));
            }
#pragma unroll
            for (int im = 0; im < 4; ++im)
#pragma unroll
                for (int jn = 0; jn < 4; ++jn)
                    MMA16816(acc[im][jn], a[im],
                             b[jn >> 1][jn & 1], b[jn >> 1][(jn & 1) + 2]);
        }
    }

    // epilogue: fp16 stores
#pragma unroll
    for (int im = 0; im < 4; ++im) {
        const int r0 = m0 + warp_m * 64 + im * 16 + (lane >> 2);
#pragma unroll
        for (int jn = 0; jn < 4; ++jn) {
            const int col = n0 + warp_n * 32 + jn * 8 + (lane & 3) * 2;
            *(__half2*)&out[(size_t)r0 * N_DIM + col] =
                __floats2half2_rn(acc[im][jn][0], acc[im][jn][1]);
            *(__half2*)&out[(size_t)(r0 + 8) * N_DIM + col] =
                __floats2half2_rn(acc[im][jn][2], acc[im][jn][3]);
        }
    }
}

// ---------------------------------------------------------------------------
// LayerNorm (+bias) + LSTM, register-resident. 128 threads / batch row.
//   Thread t owns H-elements [8t, 8t+8) of ALL 4 gates in registers.
// ---------------------------------------------------------------------------
__device__ __forceinline__ float sigmoidf_(float x) {
    return 1.0f / (1.0f + expf(-x));
}

__global__ __launch_bounds__(128)
void ln_lstm_kernel(const __half* __restrict__ gates,  // [B, 4, H] fp16
                    const float* __restrict__ c,       // [B, H]
                    const float* __restrict__ bh,      // [4H]
                    const float* __restrict__ gamma,   // [4, H]
                    const float* __restrict__ beta,    // [4, H]
                    float* __restrict__ h_new,
                    float* __restrict__ c_new) {
    const int b    = blockIdx.x;
    const int tid  = threadIdx.x;
    const int wrp  = tid >> 5;
    const int lane = tid & 31;
    const int j0   = tid * 8;

    __shared__ float rsum[4][4];   // [warp][gate]
    __shared__ float rsq [4][4];

    float v[4][8];
    float s[4], q[4];

#pragma unroll
    for (int g = 0; g < 4; ++g) {
        const __half* row = gates + (size_t)b * N_DIM + g * H_DIM + j0;
        uint4 raw = *(const uint4*)row;                  // 8 halfs
        float2 p0 = __half22float2(*(__half2*)&raw.x);
        float2 p1 = __half22float2(*(__half2*)&raw.y);
        float2 p2 = __half22float2(*(__half2*)&raw.z);
        float2 p3 = __half22float2(*(__half2*)&raw.w);
        float4 b0 = *(const float4*)&bh[g * H_DIM + j0];
        float4 b1 = *(const float4*)&bh[g * H_DIM + j0 + 4];
        v[g][0] = p0.x + b0.x; v[g][1] = p0.y + b0.y;
        v[g][2] = p1.x + b0.z; v[g][3] = p1.y + b0.w;
        v[g][4] = p2.x + b1.x; v[g][5] = p2.y + b1.y;
        v[g][6] = p3.x + b1.z; v[g][7] = p3.y + b1.w;
        float ss = 0.0f, qq = 0.0f;
#pragma unroll
        for (int i = 0; i < 8; ++i) { ss += v[g][i]; qq += v[g][i] * v[g][i]; }
        s[g] = ss; q[g] = qq;
    }

#pragma unroll
    for (int off = 16; off > 0; off >>= 1) {
#pragma unroll
        for (int g = 0; g < 4; ++g) {
            s[g] += __shfl_xor_sync(0xffffffffu, s[g], off);
            q[g] += __shfl_xor_sync(0xffffffffu, q[g], off);
        }
    }
    if (lane == 0) {
#pragma unroll
        for (int g = 0; g < 4; ++g) { rsum[wrp][g] = s[g]; rsq[wrp][g] = q[g]; }
    }
    __syncthreads();

    float mean[4], rstd[4];
    const float inv_n = 1.0f / (float)H_DIM;
#pragma unroll
    for (int g = 0; g < 4; ++g) {
        float ss = rsum[0][g] + rsum[1][g] + rsum[2][g] + rsum[3][g];
        float qq = rsq[0][g]  + rsq[1][g]  + rsq[2][g]  + rsq[3][g];
        mean[g] = ss * inv_n;
        float var = fmaxf(qq * inv_n - mean[g] * mean[g], 0.0f);
        rstd[g] = rsqrtf(var + 1e-5f);
    }

    // normalize in registers
#pragma unroll
    for (int g = 0; g < 4; ++g) {
        float4 g0 = *(const float4*)&gamma[g * H_DIM + j0];
        float4 g1 = *(const float4*)&gamma[g * H_DIM + j0 + 4];
        float4 e0 = *(const float4*)&beta[g * H_DIM + j0];
        float4 e1 = *(const float4*)&beta[g * H_DIM + j0 + 4];
        const float m = mean[g], r = rstd[g];
        v[g][0] = (v[g][0] - m) * r * g0.x + e0.x;
        v[g][1] = (v[g][1] - m) * r * g0.y + e0.y;
        v[g][2] = (v[g][2] - m) * r * g0.z + e0.z;
        v[g][3] = (v[g][3] - m) * r * g0.w + e0.w;
        v[g][4] = (v[g][4] - m) * r * g1.x + e1.x;
        v[g][5] = (v[g][5] - m) * r * g1.y + e1.y;
        v[g][6] = (v[g][6] - m) * r * g1.z + e1.z;
        v[g][7] = (v[g][7] - m) * r * g1.w + e1.w;
    }

    // LSTM elementwise
    const size_t base = (size_t)b * H_DIM + j0;
    float4 c0 = *(const float4*)&c[base];
    float4 c1 = *(const float4*)&c[base + 4];
    float cin[8] = {c0.x, c0.y, c0.z, c0.w, c1.x, c1.y, c1.z, c1.w};
    float cn[8], hn[8];
#pragma unroll
    for (int i = 0; i < 8; ++i) {
        cn[i] = sigmoidf_(v[1][i]) * cin[i] + sigmoidf_(v[0][i]) * tanhf(v[2][i]);
        hn[i] = sigmoidf_(v[3][i]) * tanhf(cn[i]);
    }
    *(float4*)&c_new[base]     = make_float4(cn[0], cn[1], cn[2], cn[3]);
    *(float4*)&c_new[base + 4] = make_float4(cn[4], cn[5], cn[6], cn[7]);
    *(float4*)&h_new[base]     = make_float4(hn[0], hn[1], hn[2], hn[3]);
    *(float4*)&h_new[base + 4] = make_float4(hn[4], hn[5], hn[6], hn[7]);
}

// ---------------------------------------------------------------------------
// Host launcher
// ---------------------------------------------------------------------------
extern "C" void kernel_launch(void* const* d_in, const int* in_sizes, int n_in,
                              void* d_out, int out_size) {
    const float* x     = (const float*)d_in[0];
    const float* h     = (const float*)d_in[1];
    const float* c     = (const float*)d_in[2];
    const float* Wi    = (const float*)d_in[3];
    const float* Wh    = (const float*)d_in[4];
    const float* bh    = (const float*)d_in[5];
    const float* gamma = (const float*)d_in[6];
    const float* beta  = (const float*)d_in[7];

    float* out   = (float*)d_out;
    float* h_new = out;
    float* c_new = out + (size_t)B_DIM * H_DIM;

    __half* gates; cudaGetSymbolAddress((void**)&gates, g_gates);
    __half* a_ptr; cudaGetSymbolAddress((void**)&a_ptr, g_Ah);
    __half* w_ptr; cudaGetSymbolAddress((void**)&w_ptr, g_Wh);

    pack_a_kernel<<<dim3(3, B_DIM), 128>>>(x, h);
    pack_w_kernel<<<dim3(K_RAW / 32, N_DIM / 32), dim3(32, 8)>>>(Wi, Wh);

    cudaFuncSetAttribute(gemm_mma_kernel,
                         cudaFuncAttributeMaxDynamicSharedMemorySize, SMEM_BYTES);
    gemm_mma_kernel<<<dim3(N_DIM / TILE_N, B_DIM / TILE_M), 256, SMEM_BYTES>>>(
        a_ptr, w_ptr, gates);

    ln_lstm_kernel<<<B_DIM, 128>>>(gates, c, bh, gamma, beta, h_new, c_new);
}